// round 3
// baseline (speedup 1.0000x reference)
#include <cuda_runtime.h>
#include <math.h>

#define HN   256
#define CINN 39
#define BN   128
#define SEQN 200
#define TN   1000
#define ON   61

// ---------------- scratch (device globals; no allocation allowed) ----------------
__device__ float g_Xp[2][SEQN][BN][HN];        // per-frame input projection + bi (NOT br)
__device__ float g_WrT[2][257][HN];            // WrT[d][i][h] = Wr_d[h][i]; row 256 = zeros (padding)
__device__ float g_block[SEQN][BN][2 * HN];    // 5-step block averages (merged fw|bw)
__device__ float g_y[SEQN][BN][ON];            // output-head pre/post scan values

// ---------------- 1) input projection: Xp[d][f][b][h] = (x[b,f]@Wi_d[h]) + bi ----------------
__global__ void __launch_bounds__(256) proj_kernel(
    const float* __restrict__ x,
    const float* __restrict__ Wi_fw, const float* __restrict__ bi_fw,
    const float* __restrict__ Wi_bw, const float* __restrict__ bi_bw)
{
    int blk = blockIdx.x;          // 0..399
    int d = blk & 1;
    int f = blk >> 1;
    const float* Wi = d ? Wi_bw : Wi_fw;
    const float* bi = d ? bi_bw : bi_fw;
    int h = threadIdx.x;

    __shared__ float xs[BN][CINN + 1];   // +1 pad
    for (int i = h; i < BN * CINN; i += blockDim.x) {
        int b = i / CINN, c = i % CINN;
        xs[b][c] = x[(b * SEQN + f) * CINN + c];
    }
    __syncthreads();

    float w[CINN];
#pragma unroll
    for (int c = 0; c < CINN; c++) w[c] = Wi[h * CINN + c];
    float bias = bi[h];

    for (int b = 0; b < BN; b++) {
        float s = 0.0f;            // dot from zero, ascending FMA (gemm-like)
#pragma unroll
        for (int c = 0; c < CINN; c++) s = __fmaf_rn(xs[b][c], w[c], s);
        g_Xp[d][f][b][h] = __fadd_rn(s, bias);   // separate rounded broadcast-add
    }
}

// ---------------- 2) transpose Wr into column-major (+1 zero pad row) ----------------
__global__ void transpose_kernel(const float* __restrict__ Wr_fw, const float* __restrict__ Wr_bw)
{
    int idx = blockIdx.x * blockDim.x + threadIdx.x;
    int total = 2 * 257 * HN;
    if (idx >= total) return;
    int d = idx / (257 * HN);
    int r = idx % (257 * HN);
    int i = r / HN;        // source column index
    int h = r % HN;        // source row index
    const float* Wr = d ? Wr_bw : Wr_fw;
    g_WrT[d][i][h] = (i < HN) ? Wr[h * HN + i] : 0.0f;
}

// ---------------- 3) recurrence: 1 CTA per (direction,batch) chain, 256 threads = neurons ---------
__global__ void __launch_bounds__(256) recur_kernel(
    const float* __restrict__ tau_m_fw, const float* __restrict__ tau_adp_fw,
    const float* __restrict__ tau_m_bw, const float* __restrict__ tau_adp_bw,
    const float* __restrict__ br_fw,   const float* __restrict__ br_bw)
{
    int d = blockIdx.x & 1;
    int b = blockIdx.x >> 1;
    int h = threadIdx.x;
    int warp = h >> 5, lane = h & 31;

    const float* tm = d ? tau_m_bw : tau_m_fw;
    const float* ta = d ? tau_adp_bw : tau_adp_fw;
    const float* brp = d ? br_bw : br_fw;
    // correctly-rounded exp of the fp32-rounded argument (matches XLA exp better than expf)
    float alpha = (float)exp((double)__fdiv_rn(-1.0f, tm[h]));
    float ro    = (float)exp((double)__fdiv_rn(-1.0f, ta[h]));
    float oma   = __fsub_rn(1.0f, alpha);
    float omro  = __fsub_rn(1.0f, ro);
    float br    = brp[h];

    const float* WrT = &g_WrT[d][0][0];

    float mem = 0.0f, spk = 0.0f, badp = 0.01f;
    float blocksum = 0.0f;
    float inp = 0.0f;

    __shared__ unsigned smask[8];
    __shared__ unsigned short slist[HN];

    unsigned lanelt = (lane == 0) ? 0u : (0xffffffffu >> (32 - lane));

    for (int t = 0; t < TN; t++) {
        // frame reload: fw changes at t%5==0 (f=t/5); bw changes at t==0 and t%5==1
        int tm5 = t % 5;
        bool reload = d ? (t == 0 || tm5 == 1) : (tm5 == 0);
        if (reload) {
            int f = d ? ((200 - (t + 4) / 5) % 200) : (t / 5);
            inp = g_Xp[d][f][b][h];
        }

        // ---- build active-neuron list from previous spikes ----
        unsigned m = __ballot_sync(0xffffffffu, spk != 0.0f);
        if (lane == 0) smask[warp] = m;
        __syncthreads();

        int cnt = 0, base = 0;
#pragma unroll
        for (int w = 0; w < 8; w++) {
            int pc = __popc(smask[w]);
            if (w < warp) base += pc;
            cnt += pc;
        }
        if (spk != 0.0f) {
            int pos = base + __popc(m & lanelt);
            slist[pos] = (unsigned short)h;
        }
        int cnt_pad = (cnt + 7) & ~7;
        if (h >= cnt && h < cnt_pad) slist[h] = (unsigned short)HN;  // points at zero row
        __syncthreads();

        // ---- sparse column gather-sum; ascending-index adds == dense ascending FMA dot ----
        float rsum = 0.0f;
        for (int k = 0; k < cnt_pad; k += 8) {
            int i0 = slist[k + 0], i1 = slist[k + 1], i2 = slist[k + 2], i3 = slist[k + 3];
            int i4 = slist[k + 4], i5 = slist[k + 5], i6 = slist[k + 6], i7 = slist[k + 7];
            float v0 = __ldg(WrT + i0 * HN + h);
            float v1 = __ldg(WrT + i1 * HN + h);
            float v2 = __ldg(WrT + i2 * HN + h);
            float v3 = __ldg(WrT + i3 * HN + h);
            float v4 = __ldg(WrT + i4 * HN + h);
            float v5 = __ldg(WrT + i5 * HN + h);
            float v6 = __ldg(WrT + i6 * HN + h);
            float v7 = __ldg(WrT + i7 * HN + h);
            rsum = __fadd_rn(rsum, v0); rsum = __fadd_rn(rsum, v1);
            rsum = __fadd_rn(rsum, v2); rsum = __fadd_rn(rsum, v3);
            rsum = __fadd_rn(rsum, v4); rsum = __fadd_rn(rsum, v5);
            rsum = __fadd_rn(rsum, v6); rsum = __fadd_rn(rsum, v7);
        }

        // ---- adaptive-LIF update; exact JAX association, NO FMA contraction ----
        // din = ((x@Wi.T + bi) + spk@Wr.T) + br
        float din = __fadd_rn(__fadd_rn(inp, rsum), br);
        badp = __fadd_rn(__fmul_rn(ro, badp), __fmul_rn(omro, spk));
        float Bth = __fadd_rn(0.01f, __fmul_rn(1.8f, badp));
        mem = __fsub_rn(__fadd_rn(__fmul_rn(mem, alpha), __fmul_rn(oma, din)),
                        __fmul_rn(Bth, spk));
        spk = (__fsub_rn(mem, Bth) > 0.0f) ? 1.0f : 0.0f;

        blocksum = __fadd_rn(blocksum, spk);
        if (tm5 == 4) {
            int s = d ? (199 - t / 5) : (t / 5);
            g_block[s][b][d * HN + h] = __fdiv_rn(blocksum, 5.0f);
            blocksum = 0.0f;
        }
        __syncthreads();   // protect smask/slist reuse next step
    }
}

// ---------------- 4) output matmul: y[s][b][o] = block[s][b]·W_out[o] + b_out[o] ----------------
#define WSTRIDE 513
__global__ void __launch_bounds__(256) outmm_kernel(
    const float* __restrict__ W_out, const float* __restrict__ b_out)
{
    int s = blockIdx.x;
    extern __shared__ float sm[];
    float* Wsm   = sm;                       // [64][513] (rows 61..63 unused)
    float* brow  = sm + 64 * WSTRIDE;        // [512]
    float* parts = brow + 512;               // [256], indexed o + 64*q

    int t = threadIdx.x;
    int o = t & 63;        // warp lanes -> distinct o -> conflict-free LDS with stride 513
    int q = t >> 6;        // 4 K-slices of 128

    for (int i = t; i < ON * 512; i += 256) {
        int oo = i >> 9, kk = i & 511;
        Wsm[oo * WSTRIDE + kk] = W_out[i];
    }
    float bo = (t < ON) ? b_out[t] : 0.0f;
    __syncthreads();

    for (int b = 0; b < BN; b++) {
        for (int i = t; i < 512; i += 256) brow[i] = g_block[s][b][i];
        __syncthreads();

        if (o < ON) {
            float p = 0.0f;
            const float* wr = Wsm + o * WSTRIDE + q * 128;
            const float* xr = brow + q * 128;
#pragma unroll 8
            for (int k = 0; k < 128; k++) p = __fmaf_rn(wr[k], xr[k], p);
            parts[o + (q << 6)] = p;
        }
        __syncthreads();

        if (t < ON) {
            float yv = __fadd_rn(
                __fadd_rn(__fadd_rn(parts[t], parts[t + 64]),
                          __fadd_rn(parts[t + 128], parts[t + 192])), bo);
            g_y[s][b][t] = yv;
        }
        __syncthreads();
    }
}

// ---------------- 5) leaky-integrator scan over s (per (b,o) chain) ----------------
__global__ void scan_kernel(const float* __restrict__ tau_m_out)
{
    int idx = blockIdx.x * blockDim.x + threadIdx.x;
    if (idx >= BN * ON) return;
    int b = idx / ON, o = idx % ON;
    float a = (float)exp((double)__fdiv_rn(-1.0f, tau_m_out[o]));
    float omA = __fsub_rn(1.0f, a);
    float mem = 0.0f;
    for (int s = 0; s < SEQN; s++) {
        mem = __fadd_rn(__fmul_rn(mem, a), __fmul_rn(omA, g_y[s][b][o]));
        g_y[s][b][o] = mem;          // in-place: now holds mem_out
    }
}

// ---------------- 6) log_softmax per (s,b) row: one warp per row ----------------
__global__ void __launch_bounds__(256) softmax_kernel(float* __restrict__ out)
{
    int row = blockIdx.x * (blockDim.x >> 5) + (threadIdx.x >> 5);
    if (row >= SEQN * BN) return;
    int lane = threadIdx.x & 31;
    const float* yr = &g_y[0][0][0] + row * ON;

    float v0 = (lane < ON)      ? yr[lane]      : -1e30f;
    float v1 = (lane + 32 < ON) ? yr[lane + 32] : -1e30f;
    float mx = fmaxf(v0, v1);
#pragma unroll
    for (int off = 16; off; off >>= 1) mx = fmaxf(mx, __shfl_xor_sync(0xffffffffu, mx, off));
    float e = ((lane < ON) ? expf(__fsub_rn(v0, mx)) : 0.0f)
            + ((lane + 32 < ON) ? expf(__fsub_rn(v1, mx)) : 0.0f);
#pragma unroll
    for (int off = 16; off; off >>= 1) e += __shfl_xor_sync(0xffffffffu, e, off);
    float lse = __fadd_rn(mx, logf(e));
    if (lane < ON)      out[row * ON + lane]      = __fsub_rn(v0, lse);
    if (lane + 32 < ON) out[row * ON + lane + 32] = __fsub_rn(v1, lse);
}

// ---------------- host launcher ----------------
extern "C" void kernel_launch(void* const* d_in, const int* in_sizes, int n_in,
                              void* d_out, int out_size)
{
    const float* x         = (const float*)d_in[0];
    const float* Wi_fw     = (const float*)d_in[1];
    const float* bi_fw     = (const float*)d_in[2];
    const float* Wr_fw     = (const float*)d_in[3];
    const float* br_fw     = (const float*)d_in[4];
    const float* tau_m_fw  = (const float*)d_in[5];
    const float* tau_adp_fw= (const float*)d_in[6];
    const float* Wi_bw     = (const float*)d_in[7];
    const float* bi_bw     = (const float*)d_in[8];
    const float* Wr_bw     = (const float*)d_in[9];
    const float* br_bw     = (const float*)d_in[10];
    const float* tau_m_bw  = (const float*)d_in[11];
    const float* tau_adp_bw= (const float*)d_in[12];
    const float* W_out     = (const float*)d_in[13];
    const float* b_out     = (const float*)d_in[14];
    const float* tau_m_out = (const float*)d_in[15];

    proj_kernel<<<2 * SEQN, 256>>>(x, Wi_fw, bi_fw, Wi_bw, bi_bw);
    transpose_kernel<<<(2 * 257 * HN + 255) / 256, 256>>>(Wr_fw, Wr_bw);
    recur_kernel<<<2 * BN, 256>>>(tau_m_fw, tau_adp_fw, tau_m_bw, tau_adp_bw, br_fw, br_bw);

    size_t smem = (size_t)(64 * WSTRIDE + 512 + 256) * sizeof(float);
    static_assert(64 * WSTRIDE * 4 < 200 * 1024, "smem fits");
    cudaFuncSetAttribute(outmm_kernel, cudaFuncAttributeMaxDynamicSharedMemorySize, (int)smem);
    outmm_kernel<<<SEQN, 256, smem>>>(W_out, b_out);

    scan_kernel<<<(BN * ON + 255) / 256, 256>>>(tau_m_out);
    softmax_kernel<<<(SEQN * BN + 7) / 8, 256>>>((float*)d_out);
}